// round 6
// baseline (speedup 1.0000x reference)
#include <cuda_runtime.h>
#include <cstdint>

// QConv1d via mma.sync tf32 implicit GEMM, conflict-free K-permutation.
// out[n,o,l] = 0.125 * sum_{c,k} x[n,c,l+k-4] * w[o,c,k] + bias[o]
// GEMM: M = 256 l-positions per tile, N = 64 (o), K = 576.
//
// K-step s=(a,b): fragment column p in 0..7 -> kidx = (8b+p)*9 + a
// (tap a fixed within a step, 8 consecutive channels). A-LDS bank =
// g + 8*tig + a (mod 32): conflict-free. B pre-packed in matching order.
// 512 threads = 16 warps, warp grid 8(M) x 2(N), 32x32 C per warp.

#define N_BATCH 8
#define C_IN    64
#define L_IN    16384
#define O_OUT   64
#define KSZ     9
#define PADK    4
#define SCALEF  0.125f

#define THREADS 512
#define TILE_L  256
#define TPERN   (L_IN / TILE_L)               // 64
#define NTILES  (N_BATCH * TPERN)             // 512
#define GRID    148

#define KTOT    (C_IN * KSZ)                  // 576
#define KSTEPS  (KTOT / 8)                    // 72

#define XS_STRIDE 264                         // floats; 264 mod 32 = 8
#define XS_ROWB   (XS_STRIDE * 4)             // 1056 bytes per c-row
#define XS_FLOATS (C_IN * XS_STRIDE)          // 16896

// SMEM layout (bytes)
#define PK_BYTES   (KSTEPS * 256 * 8)         // 147456: [s][nB][nt][lane] float2
#define SM_PK      0
#define SM_XS      PK_BYTES
#define SM_BIAS    (SM_XS + XS_FLOATS * 4)    // 215040
#define SM_TOTAL   (SM_BIAS + O_OUT * 4)      // 215296

__device__ __forceinline__ uint32_t smem_u32(const void* p) {
    uint32_t a;
    asm("{ .reg .u64 t; cvta.to.shared.u64 t, %1; cvt.u32.u64 %0, t; }" : "=r"(a) : "l"(p));
    return a;
}

__device__ __forceinline__ uint32_t f2tf32(float f) {
    uint32_t r;
    asm("cvt.rna.tf32.f32 %0, %1;" : "=r"(r) : "f"(f));
    return r;
}

__device__ __forceinline__ uint32_t lds_b32(uint32_t a) {
    uint32_t v;
    asm volatile("ld.shared.b32 %0, [%1];" : "=r"(v) : "r"(a));
    return v;
}

__device__ __forceinline__ void lds_v2(uint32_t a, uint32_t& v0, uint32_t& v1) {
    asm volatile("ld.shared.v2.b32 {%0, %1}, [%2];" : "=r"(v0), "=r"(v1) : "r"(a));
}

__device__ __forceinline__ void mma_tf32(float* c, const uint32_t* a, uint32_t b0, uint32_t b1) {
    asm volatile(
        "mma.sync.aligned.m16n8k8.row.col.f32.tf32.tf32.f32 "
        "{%0,%1,%2,%3}, {%4,%5,%6,%7}, {%8,%9}, {%0,%1,%2,%3};"
        : "+f"(c[0]), "+f"(c[1]), "+f"(c[2]), "+f"(c[3])
        : "r"(a[0]), "r"(a[1]), "r"(a[2]), "r"(a[3]), "r"(b0), "r"(b1));
}

__global__ void __launch_bounds__(THREADS, 1)
qconv1d_mma(const float* __restrict__ x, const float* __restrict__ w,
            const float* __restrict__ bias, float* __restrict__ out)
{
    extern __shared__ char smem[];
    float* xs      = (float*)(smem + SM_XS);
    float* bias_sm = (float*)(smem + SM_BIAS);

    const int tid  = threadIdx.x;
    const int wid  = tid >> 5;
    const int lane = tid & 31;
    const int mBlk = wid & 7;        // M block: rows [mBlk*32, +32) of 256
    const int nBlk = wid >> 3;       // N block: cols [nBlk*32, +32) of 64
    const int g    = lane >> 2;      // group id 0..7 (m row within fragment)
    const int tig  = lane & 3;       // thread in group (k position)

    // ---- pack weights in permuted fragment order (once per persistent CTA) ----
    // pk float2 index: s*256 + nB*128 + nt*32 + lane, s = a*8 + b
    // o = nB*32 + nt*8 + (lane>>2); col p=tig -> kidx=(8b+tig)*9+a; p=tig+4 -> +36
    {
        uint2* pk = (uint2*)(smem + SM_PK);
        for (int i = tid; i < KSTEPS * 256; i += THREADS) {
            int li = i & 31;
            int nt = (i >> 5) & 3;
            int nB = (i >> 7) & 1;
            int s  = i >> 8;
            int b  = s & 7;
            int a  = s >> 3;
            int o  = nB * 32 + nt * 8 + (li >> 2);
            int c0 = 8 * b + (li & 3);
            uint2 v;
            v.x = f2tf32(w[o * KTOT + c0 * KSZ + a]);
            v.y = f2tf32(w[o * KTOT + (c0 + 4) * KSZ + a]);
            pk[i] = v;
        }
        if (tid < O_OUT) bias_sm[tid] = bias[tid];
    }

    const uint32_t sbase = smem_u32(smem);
    // A base: row (mBlk*32 + g), channel tig (within each b-group of 8)
    const uint32_t xsA = sbase + SM_XS + (uint32_t)(mBlk * 32 + g) * 4 + (uint32_t)tig * XS_ROWB;
    const uint32_t pkB = sbase + SM_PK + (uint32_t)(nBlk * 128 + lane) * 8;

    for (int t = blockIdx.x; t < NTILES; t += GRID) {
        const int n     = t / TPERN;
        const int tileL = (t % TPERN) * TILE_L;
        const float* xn = x + (size_t)n * C_IN * L_IN;

        // ---- fill x tile [64 c][264 l] (l = tileL-4 .. tileL+259), tf32, zero-padded ----
        for (int i = tid; i < XS_FLOATS; i += THREADS) {
            int c = i / XS_STRIDE;
            int j = i - c * XS_STRIDE;
            int gl = tileL - PADK + j;
            float v = (gl >= 0 && gl < L_IN) ? xn[(size_t)c * L_IN + gl] : 0.0f;
            xs[i] = __uint_as_float(f2tf32(v));
        }
        __syncthreads();

        float acc[2][4][4];
        #pragma unroll
        for (int mt = 0; mt < 2; ++mt)
            #pragma unroll
            for (int nt = 0; nt < 4; ++nt)
                #pragma unroll
                for (int r = 0; r < 4; ++r) acc[mt][nt][r] = 0.0f;

        #pragma unroll 1
        for (int a = 0; a < KSZ; ++a) {        // kernel tap (9)
            const uint32_t pAa = xsA + (uint32_t)a * 4;
            const uint32_t pBa = pkB + (uint32_t)a * (8 * 2048);
            #pragma unroll
            for (int b = 0; b < 8; ++b) {      // channel group of 8
                const uint32_t pA = pAa + (uint32_t)b * (8 * XS_ROWB);
                uint32_t af[2][4];
                #pragma unroll
                for (int mt = 0; mt < 2; ++mt) {
                    const uint32_t p = pA + mt * 64;
                    af[mt][0] = lds_b32(p);                   // row g,    c0+tig
                    af[mt][1] = lds_b32(p + 32);              // row g+8
                    af[mt][2] = lds_b32(p + 4 * XS_ROWB);     // c0+4+tig
                    af[mt][3] = lds_b32(p + 4 * XS_ROWB + 32);
                }
                #pragma unroll
                for (int nt = 0; nt < 4; ++nt) {
                    uint32_t b0, b1;
                    lds_v2(pBa + b * 2048 + nt * 256, b0, b1);
                    mma_tf32(acc[0][nt], af[0], b0, b1);
                    mma_tf32(acc[1][nt], af[1], b0, b1);
                }
            }
        }
        __syncthreads();   // all warps done reading xs before next tile refill

        // ---- epilogue: scale + bias, direct stores ----
        float* ob = out + (size_t)n * O_OUT * L_IN + tileL;
        #pragma unroll
        for (int mt = 0; mt < 2; ++mt) {
            const int r0 = mBlk * 32 + mt * 16 + g;
            #pragma unroll
            for (int nt = 0; nt < 4; ++nt) {
                const int o0 = nBlk * 32 + nt * 8 + tig * 2;
                const float b0 = bias_sm[o0], b1 = bias_sm[o0 + 1];
                ob[(size_t)o0 * L_IN + r0]           = acc[mt][nt][0] * SCALEF + b0;
                ob[(size_t)(o0 + 1) * L_IN + r0]     = acc[mt][nt][1] * SCALEF + b1;
                ob[(size_t)o0 * L_IN + r0 + 8]       = acc[mt][nt][2] * SCALEF + b0;
                ob[(size_t)(o0 + 1) * L_IN + r0 + 8] = acc[mt][nt][3] * SCALEF + b1;
            }
        }
    }
}

extern "C" void kernel_launch(void* const* d_in, const int* in_sizes, int n_in,
                              void* d_out, int out_size)
{
    const float* x    = (const float*)d_in[0];
    const float* w    = (const float*)d_in[1];
    const float* bias = (const float*)d_in[2];
    float* out        = (float*)d_out;

    cudaFuncSetAttribute(qconv1d_mma,
                         cudaFuncAttributeMaxDynamicSharedMemorySize, SM_TOTAL);
    qconv1d_mma<<<GRID, THREADS, SM_TOTAL>>>(x, w, bias, out);
}

// round 7
// speedup vs baseline: 1.6673x; 1.6673x over previous
#include <cuda_runtime.h>
#include <cuda_fp16.h>
#include <cstdint>

// QConv1d via mma.sync f16 m16n8k16 implicit GEMM.
// out[n,o,l] = 0.125 * sum_{c,k} x[n,c,l+k-4] * w[o,c,k] + bias[o]
// GEMM: M = 256 l-positions per tile, N = 64 (o), K = 576.
//
// K permuted: step s=(a,cg) covers 16 channels [16cg,16cg+16) at tap a.
// x stored channel-pair interleaved fp16x2: xs2[cp][l] = (x[2cp][l], x[2cp+1][l])
// -> each A fragment reg is ONE aligned 32-bit LDS, conflict-free
//    (stride 264 words = 8 mod 32 -> bank = 8*tig + g + const).
// B (weights) pre-packed in fragment order once per persistent CTA.
// 512 threads = 16 warps, warp grid 8(M) x 2(N), 32x32 C per warp.

#define N_BATCH 8
#define C_IN    64
#define L_IN    16384
#define O_OUT   64
#define KSZ     9
#define PADK    4
#define SCALEF  0.125f

#define THREADS 512
#define TILE_L  256
#define TPERN   (L_IN / TILE_L)               // 64
#define NTILES  (N_BATCH * TPERN)             // 512
#define GRID    148

#define KTOT    (C_IN * KSZ)                  // 576
#define NSTEPS  36                            // 9 taps x 4 channel-groups, K=16 each

#define XS2_STRIDE 264                        // fp16x2 words per row; 264 % 32 == 8
#define XS2_ROWB   (XS2_STRIDE * 4)           // 1056 bytes
#define XS2_WORDS  (32 * XS2_STRIDE)          // 8448 (32 channel-pair rows)

// SMEM layout (bytes)
#define PK_BYTES   (NSTEPS * 256 * 8)         // 73728: [s][nB][nt][lane] uint2 (b0,b1)
#define SM_PK      0
#define SM_XS      PK_BYTES
#define SM_BIAS    (SM_XS + XS2_WORDS * 4)    // 107520
#define SM_TOTAL   (SM_BIAS + O_OUT * 4)      // 107776

__device__ __forceinline__ uint32_t smem_u32(const void* p) {
    uint32_t a;
    asm("{ .reg .u64 t; cvta.to.shared.u64 t, %1; cvt.u32.u64 %0, t; }" : "=r"(a) : "l"(p));
    return a;
}

__device__ __forceinline__ uint32_t lds_b32(uint32_t a) {
    uint32_t v;
    asm volatile("ld.shared.b32 %0, [%1];" : "=r"(v) : "r"(a));
    return v;
}

__device__ __forceinline__ void lds_v2(uint32_t a, uint32_t& v0, uint32_t& v1) {
    asm volatile("ld.shared.v2.b32 {%0, %1}, [%2];" : "=r"(v0), "=r"(v1) : "r"(a));
}

__device__ __forceinline__ uint32_t packh2(float a, float b) {
    __half2 h = __floats2half2_rn(a, b);      // low = a, high = b
    return *reinterpret_cast<uint32_t*>(&h);
}

__device__ __forceinline__ void mma_f16(float* c, const uint32_t* a, uint32_t b0, uint32_t b1) {
    asm volatile(
        "mma.sync.aligned.m16n8k16.row.col.f32.f16.f16.f32 "
        "{%0,%1,%2,%3}, {%4,%5,%6,%7}, {%8,%9}, {%0,%1,%2,%3};"
        : "+f"(c[0]), "+f"(c[1]), "+f"(c[2]), "+f"(c[3])
        : "r"(a[0]), "r"(a[1]), "r"(a[2]), "r"(a[3]), "r"(b0), "r"(b1));
}

__global__ void __launch_bounds__(THREADS, 1)
qconv1d_mma(const float* __restrict__ x, const float* __restrict__ w,
            const float* __restrict__ bias, float* __restrict__ out)
{
    extern __shared__ char smem[];
    uint32_t* xs2     = (uint32_t*)(smem + SM_XS);
    float*    bias_sm = (float*)(smem + SM_BIAS);

    const int tid  = threadIdx.x;
    const int wid  = tid >> 5;
    const int lane = tid & 31;
    const int mBlk = wid & 7;        // M block: rows [mBlk*32, +32) of 256
    const int nBlk = wid >> 3;       // N block: cols [nBlk*32, +32) of 64
    const int g    = lane >> 2;      // group id 0..7
    const int tig  = lane & 3;       // thread in group

    // ---- pack weights in f16 fragment order (once per persistent CTA) ----
    // uint2 index: s*256 + nB*128 + nt*32 + lane, s = a*4 + cg
    // o = nB*32 + nt*8 + g; c0 = cg*16 + 2*tig
    // b0 = (w[o][c0][a], w[o][c0+1][a]); b1 = (w[o][c0+8][a], w[o][c0+9][a])
    {
        uint2* pk = (uint2*)(smem + SM_PK);
        for (int i = tid; i < NSTEPS * 256; i += THREADS) {
            int li = i & 31;
            int nt = (i >> 5) & 3;
            int nB = (i >> 7) & 1;
            int s  = i >> 8;
            int a  = s >> 2;
            int cg = s & 3;
            int o  = nB * 32 + nt * 8 + (li >> 2);
            int c0 = cg * 16 + 2 * (li & 3);
            const float* wr = w + o * KTOT + a;
            uint2 v;
            v.x = packh2(wr[c0 * KSZ],       wr[(c0 + 1) * KSZ]);
            v.y = packh2(wr[(c0 + 8) * KSZ], wr[(c0 + 9) * KSZ]);
            pk[i] = v;
        }
        if (tid < O_OUT) bias_sm[tid] = bias[tid];
    }

    const uint32_t sbase = smem_u32(smem);
    // A base: channel-pair row tig (within each cg block of 8 rows), m word (mBlk*32+g)
    const uint32_t xsA = sbase + SM_XS + (uint32_t)tig * XS2_ROWB + (uint32_t)(mBlk * 32 + g) * 4;
    const uint32_t pkB = sbase + SM_PK + (uint32_t)(nBlk * 128 + lane) * 8;

    for (int t = blockIdx.x; t < NTILES; t += GRID) {
        const int n     = t / TPERN;
        const int tileL = (t % TPERN) * TILE_L;
        const float* xn = x + (size_t)n * C_IN * L_IN;

        // ---- fill xs2 [32 cp][264 l-words], l = tileL-4+j, fp16x2, zero-padded ----
        for (int i = tid; i < XS2_WORDS; i += THREADS) {
            int cp = i / XS2_STRIDE;
            int j  = i - cp * XS2_STRIDE;
            int gl = tileL - PADK + j;
            float v0 = 0.0f, v1 = 0.0f;
            if (gl >= 0 && gl < L_IN) {
                const float* xr = xn + (size_t)(2 * cp) * L_IN + gl;
                v0 = xr[0];
                v1 = xr[L_IN];
            }
            xs2[i] = packh2(v0, v1);
        }
        __syncthreads();

        float acc[2][4][4];
        #pragma unroll
        for (int mt = 0; mt < 2; ++mt)
            #pragma unroll
            for (int nt = 0; nt < 4; ++nt)
                #pragma unroll
                for (int r = 0; r < 4; ++r) acc[mt][nt][r] = 0.0f;

        #pragma unroll 1
        for (int a = 0; a < KSZ; ++a) {            // tap
            const uint32_t pAa = xsA + (uint32_t)a * 4;
            const uint32_t pBa = pkB + (uint32_t)a * (4 * 2048);
            #pragma unroll
            for (int cg = 0; cg < 4; ++cg) {       // 16-channel group
                const uint32_t pA = pAa + (uint32_t)cg * (8 * XS2_ROWB);
                uint32_t af[2][4];
                #pragma unroll
                for (int mt = 0; mt < 2; ++mt) {
                    const uint32_t p = pA + mt * 64;
                    af[mt][0] = lds_b32(p);                       // row g,  ch c0+2tig(+1)
                    af[mt][1] = lds_b32(p + 32);                  // row g+8
                    af[mt][2] = lds_b32(p + 4 * XS2_ROWB);        // ch +8
                    af[mt][3] = lds_b32(p + 4 * XS2_ROWB + 32);
                }
                #pragma unroll
                for (int nt = 0; nt < 4; ++nt) {
                    uint32_t b0, b1;
                    lds_v2(pBa + cg * 2048 + nt * 256, b0, b1);
                    mma_f16(acc[0][nt], af[0], b0, b1);
                    mma_f16(acc[1][nt], af[1], b0, b1);
                }
            }
        }
        __syncthreads();   // all warps done reading xs2 before next tile refill

        // ---- epilogue: scale + bias, direct stores ----
        float* ob = out + (size_t)n * O_OUT * L_IN + tileL;
        #pragma unroll
        for (int mt = 0; mt < 2; ++mt) {
            const int r0 = mBlk * 32 + mt * 16 + g;
            #pragma unroll
            for (int nt = 0; nt < 4; ++nt) {
                const int o0 = nBlk * 32 + nt * 8 + tig * 2;
                const float b0 = bias_sm[o0], b1 = bias_sm[o0 + 1];
                ob[(size_t)o0 * L_IN + r0]           = acc[mt][nt][0] * SCALEF + b0;
                ob[(size_t)(o0 + 1) * L_IN + r0]     = acc[mt][nt][1] * SCALEF + b1;
                ob[(size_t)o0 * L_IN + r0 + 8]       = acc[mt][nt][2] * SCALEF + b0;
                ob[(size_t)(o0 + 1) * L_IN + r0 + 8] = acc[mt][nt][3] * SCALEF + b1;
            }
        }
    }
}

extern "C" void kernel_launch(void* const* d_in, const int* in_sizes, int n_in,
                              void* d_out, int out_size)
{
    const float* x    = (const float*)d_in[0];
    const float* w    = (const float*)d_in[1];
    const float* bias = (const float*)d_in[2];
    float* out        = (float*)d_out;

    cudaFuncSetAttribute(qconv1d_mma,
                         cudaFuncAttributeMaxDynamicSharedMemorySize, SM_TOTAL);
    qconv1d_mma<<<GRID, THREADS, SM_TOTAL>>>(x, w, bias, out);
}